// round 14
// baseline (speedup 1.0000x reference)
#include <cuda_runtime.h>
#include <cuda_bf16.h>
#include <cuda_fp16.h>
#include <stdint.h>

#define C 64
#define H 8
#define MAXN 100000
#define NEG_SLOPE 0.01f
#define TILE 256          // nodes per tile in phase A
#define XPAD 65           // smem row stride in floats (conflict-free scalar LDS)
#define THREADS 256

// Compressed node tables: one float4 (16B) per node per role:
//   .x = p (fp32), .y = half2(q0,q1), .z = half2(q2,q3), .w unused.
// 100k * 16B * 2 = 3.2 MB -> L2-resident during the edge phase.
__device__ float4 g_T0[MAXN];
__device__ float4 g_T1[MAXN];

// Software grid-barrier counter. Monotonic across graph replays: each launch
// computes its own target as (old/gridDim + 1)*gridDim, so no reset kernel is
// needed. Replays rewrite the tables with bit-identical values, so determinism
// holds on every call.
__device__ unsigned g_arrive;

// Dynamic smem layout: [ s_x: TILE*XPAD floats ][ s_c: C*12 floats ][ s_g: H ]
#define SMEM_FLOATS (TILE * XPAD + C * 12 + H)

__global__ void fused_kernel(const float* __restrict__ x,
                             const int*   __restrict__ edge_index,
                             const float* __restrict__ sf,
                             const int*   __restrict__ li_ptr,
                             const float* __restrict__ psi_w,
                             const float* __restrict__ psi_b,
                             const float* __restrict__ delta_w,
                             const float* __restrict__ uvec,
                             const float* __restrict__ gamma_h,
                             float* __restrict__ out,
                             int n_nodes, int n_edges)
{
    extern __shared__ float smem[];
    float* s_x = smem;                       // TILE*XPAD
    float* s_c = smem + TILE * XPAD;         // C*12, 16B-aligned
    float* s_g = s_c + C * 12;               // H

    const int tid = threadIdx.x;
    const int li  = li_ptr[0];

    if (tid < H) s_g[tid] = gamma_h[li * H + tid];

    // Coefficient table [j][12] = {b1, w0..w3, b2, w0'..w3', pad, pad}
    if (tid < C) {
        const int j = tid;
        float* c = &s_c[j * 12];
        c[0] = psi_b[j] + delta_w[li * 2 * C + j] + uvec[li * 2 * C + j];
        #pragma unroll
        for (int k = 0; k < 4; k++) c[1 + k] = psi_w[j * 4 + k];
        c[5] = psi_b[C + j] + delta_w[li * 2 * C + C + j] + uvec[li * 2 * C + C + j];
        #pragma unroll
        for (int k = 0; k < 4; k++) c[6 + k] = psi_w[(C + j) * 4 + k];
        c[10] = 0.f; c[11] = 0.f;
    }
    __syncthreads();

    // ---------------- Phase A: node precompute (grid-stride over tiles) ----
    const int n_tiles = (n_nodes + TILE - 1) / TILE;
    const float4* x4 = reinterpret_cast<const float4*>(x);

    for (int t = blockIdx.x; t < n_tiles; t += gridDim.x) {
        const int node0 = t * TILE;

        // Coalesced stage of the x tile (TILE nodes x 16 float4)
        for (int i = tid; i < TILE * 16; i += THREADS) {
            const int n  = i >> 4;
            const int j4 = i & 15;
            if (node0 + n < n_nodes) {
                float4 v = x4[(size_t)(node0 + n) * 16 + j4];
                float* dst = &s_x[n * XPAD + j4 * 4];
                dst[0] = v.x; dst[1] = v.y; dst[2] = v.z; dst[3] = v.w;
            }
        }
        __syncthreads();

        const int node = node0 + tid;
        if (node < n_nodes) {
            const float* xr = &s_x[tid * XPAD];
            float a0 = 0.f, a1 = 0.f, a2 = 0.f, a3 = 0.f, a4 = 0.f;
            float a5 = 0.f, a6 = 0.f, a7 = 0.f, a8 = 0.f, a9 = 0.f;

            #pragma unroll 8
            for (int j = 0; j < C; j++) {
                const float xv = xr[j];
                const float4* c4 = reinterpret_cast<const float4*>(&s_c[j * 12]);
                const float4 cA = c4[0];
                const float4 cB = c4[1];
                const float4 cC = c4[2];
                a0 = fmaf(xv, cA.x, a0);
                a1 = fmaf(xv, cA.y, a1);
                a2 = fmaf(xv, cA.z, a2);
                a3 = fmaf(xv, cA.w, a3);
                a4 = fmaf(xv, cB.x, a4);
                a5 = fmaf(xv, cB.y, a5);
                a6 = fmaf(xv, cB.z, a6);
                a7 = fmaf(xv, cB.w, a7);
                a8 = fmaf(xv, cC.x, a8);
                a9 = fmaf(xv, cC.y, a9);
            }

            __half2 q01  = __floats2half2_rn(a1, a2);
            __half2 q23  = __floats2half2_rn(a3, a4);
            __half2 q01b = __floats2half2_rn(a6, a7);
            __half2 q23b = __floats2half2_rn(a8, a9);
            float4 t0, t1;
            t0.x = a0;
            t0.y = __uint_as_float(*reinterpret_cast<unsigned*>(&q01));
            t0.z = __uint_as_float(*reinterpret_cast<unsigned*>(&q23));
            t0.w = 0.f;
            t1.x = a5;
            t1.y = __uint_as_float(*reinterpret_cast<unsigned*>(&q01b));
            t1.z = __uint_as_float(*reinterpret_cast<unsigned*>(&q23b));
            t1.w = 0.f;
            g_T0[node] = t0;
            g_T1[node] = t1;
        }
        __syncthreads();   // before next tile reuses s_x
    }

    // ---------------- Software grid barrier (bounded spin: cannot hang) ----
    if (tid == 0) {
        __threadfence();                                // publish table writes
        unsigned old = atomicAdd(&g_arrive, 1u);
        unsigned target = (old / gridDim.x + 1u) * gridDim.x;
        // Legit wait is <100us; bound ~4M*32ns ~= 130ms. If ever hit, we
        // proceed and produce a measurable wrong answer instead of a
        // container-killing hang (diagnosable via rel_err).
        unsigned spins = 0;
        while (*((volatile unsigned*)&g_arrive) < target && spins < 4000000u) {
            __nanosleep(32);
            spins++;
        }
        __threadfence();                                // acquire
    }
    __syncthreads();

    // ---------------- Phase B: edges (grid-stride) -------------------------
    const float g0 = s_g[0], g1 = s_g[1], g2 = s_g[2], g3 = s_g[3];
    const float g4 = s_g[4], g5 = s_g[5], g6 = s_g[6], g7 = s_g[7];

    const int stride = gridDim.x * THREADS;
    for (int e = blockIdx.x * THREADS + tid; e < n_edges; e += stride) {
        const int row = __ldcs(&edge_index[e]);
        const int col = __ldcs(&edge_index[n_edges + e]);

        const float4 f  = __ldcs(reinterpret_cast<const float4*>(sf) + e);
        const float4 R  = __ldg(&g_T0[row]);
        const float4 Cc = __ldg(&g_T1[col]);

        const __half2 rq01 = *reinterpret_cast<const __half2*>(&R.y);
        const __half2 rq23 = *reinterpret_cast<const __half2*>(&R.z);
        const __half2 cq01 = *reinterpret_cast<const __half2*>(&Cc.y);
        const __half2 cq23 = *reinterpret_cast<const __half2*>(&Cc.z);

        const float2 q01 = __half22float2(__hadd2(rq01, cq01));
        const float2 q23 = __half22float2(__hadd2(rq23, cq23));

        float s = R.x + Cc.x;
        s = fmaf(f.x, q01.x, s);
        s = fmaf(f.y, q01.y, s);
        s = fmaf(f.z, q23.x, s);
        s = fmaf(f.w, q23.y, s);

        const float base = (s > 0.f) ? s : NEG_SLOPE * s;

        float4* op = reinterpret_cast<float4*>(out + (size_t)e * H);
        __stcs(op + 0, make_float4(g0 * base, g1 * base, g2 * base, g3 * base));
        __stcs(op + 1, make_float4(g4 * base, g5 * base, g6 * base, g7 * base));
    }
}

// ---------------------------------------------------------------------------
// Launch. Input order: x, edge_index, structural_features, layer_idx,
// psi_w, psi_b, delta_w, u, gamma_h.
// ---------------------------------------------------------------------------
extern "C" void kernel_launch(void* const* d_in, const int* in_sizes, int n_in,
                              void* d_out, int out_size)
{
    const float* x    = (const float*)d_in[0];
    const int*   ei   = (const int*)d_in[1];
    const float* sf   = (const float*)d_in[2];
    const int*   li   = (const int*)d_in[3];
    const float* pw   = (const float*)d_in[4];
    const float* pb   = (const float*)d_in[5];
    const float* dw   = (const float*)d_in[6];
    const float* uu   = (const float*)d_in[7];
    const float* gh   = (const float*)d_in[8];
    float*       out  = (float*)d_out;

    const int n_nodes = in_sizes[0] / C;
    const int n_edges = in_sizes[1] / 2;

    const int smem_bytes = SMEM_FLOATS * (int)sizeof(float);   // ~69.7 KB

    // Opt in to >48KB dynamic smem (idempotent host call; free at replay)
    cudaFuncSetAttribute(fused_kernel,
                         cudaFuncAttributeMaxDynamicSharedMemorySize, smem_bytes);

    // Size the grid to guaranteed full residency (software barrier requirement)
    int blocks_per_sm = 0;
    cudaOccupancyMaxActiveBlocksPerMultiprocessor(&blocks_per_sm, fused_kernel,
                                                  THREADS, smem_bytes);
    if (blocks_per_sm < 1) blocks_per_sm = 1;

    int dev = 0, n_sm = 148;
    cudaGetDevice(&dev);
    cudaDeviceGetAttribute(&n_sm, cudaDevAttrMultiProcessorCount, dev);

    int blocks = n_sm * blocks_per_sm;

    // Never launch more blocks than there is work for both phases combined
    // (degenerate-shape safety; no effect at the benchmarked size).
    int tiles = (n_nodes + TILE - 1) / TILE;
    int eblocks = (n_edges + THREADS - 1) / THREADS;
    int max_useful = (tiles > eblocks) ? tiles : eblocks;
    if (blocks > max_useful) blocks = max_useful;

    fused_kernel<<<blocks, THREADS, smem_bytes>>>(
        x, ei, sf, li, pw, pb, dw, uu, gh, out, n_nodes, n_edges);
}

// round 15
// speedup vs baseline: 1.3839x; 1.3839x over previous
#include <cuda_runtime.h>
#include <cuda_bf16.h>
#include <cuda_fp16.h>
#include <stdint.h>

#define C 64
#define H 8
#define MAXN 100000
#define NEG_SLOPE 0.01f
#define TILE 128          // nodes per block in node kernel
#define XPAD 65           // smem row stride in floats (conflict-free scalar LDS)

// Compressed node tables: one float4 (16B) per node per role:
//   .x = p (fp32), .y = half2(q0,q1), .z = half2(q2,q3), .w unused.
// 100k * 16B * 2 = 3.2 MB -> L2-resident during the edge kernel.
__device__ float4 g_T0[MAXN];
__device__ float4 g_T1[MAXN];

// ---------------------------------------------------------------------------
// Kernel 1: per-node precompute, thread-per-node with smem-transposed x tile.
// (Proven ~5us in R11; warp-shuffle-free.)
// ---------------------------------------------------------------------------
__global__ void node_precompute(const float* __restrict__ x,
                                const float* __restrict__ psi_w,
                                const float* __restrict__ psi_b,
                                const float* __restrict__ delta_w,
                                const float* __restrict__ uvec,
                                const int*   __restrict__ li_ptr,
                                int n_nodes)
{
    __shared__ float s_x[TILE * XPAD];                 // 33.3 KB
    __shared__ __align__(16) float s_c[C * 12];        // 3 KB

    const int tid = threadIdx.x;
    const int li  = li_ptr[0];

    if (tid < C) {
        const int j = tid;
        float* c = &s_c[j * 12];
        c[0] = psi_b[j] + delta_w[li * 2 * C + j] + uvec[li * 2 * C + j];
        #pragma unroll
        for (int k = 0; k < 4; k++) c[1 + k] = psi_w[j * 4 + k];
        c[5] = psi_b[C + j] + delta_w[li * 2 * C + C + j] + uvec[li * 2 * C + C + j];
        #pragma unroll
        for (int k = 0; k < 4; k++) c[6 + k] = psi_w[(C + j) * 4 + k];
        c[10] = 0.f; c[11] = 0.f;
    }

    const int node0 = blockIdx.x * TILE;

    const float4* x4 = reinterpret_cast<const float4*>(x);
    for (int i = tid; i < TILE * 16; i += blockDim.x) {
        const int n  = i >> 4;
        const int j4 = i & 15;
        if (node0 + n < n_nodes) {
            float4 v = x4[(size_t)(node0 + n) * 16 + j4];
            float* dst = &s_x[n * XPAD + j4 * 4];
            dst[0] = v.x; dst[1] = v.y; dst[2] = v.z; dst[3] = v.w;
        }
    }
    __syncthreads();

    const int node = node0 + tid;
    if (node >= n_nodes) return;

    const float* xr = &s_x[tid * XPAD];
    float a0 = 0.f, a1 = 0.f, a2 = 0.f, a3 = 0.f, a4 = 0.f;
    float a5 = 0.f, a6 = 0.f, a7 = 0.f, a8 = 0.f, a9 = 0.f;

    #pragma unroll 8
    for (int j = 0; j < C; j++) {
        const float xv = xr[j];
        const float4* c4 = reinterpret_cast<const float4*>(&s_c[j * 12]);
        const float4 cA = c4[0];
        const float4 cB = c4[1];
        const float4 cC = c4[2];
        a0 = fmaf(xv, cA.x, a0);
        a1 = fmaf(xv, cA.y, a1);
        a2 = fmaf(xv, cA.z, a2);
        a3 = fmaf(xv, cA.w, a3);
        a4 = fmaf(xv, cB.x, a4);
        a5 = fmaf(xv, cB.y, a5);
        a6 = fmaf(xv, cB.z, a6);
        a7 = fmaf(xv, cB.w, a7);
        a8 = fmaf(xv, cC.x, a8);
        a9 = fmaf(xv, cC.y, a9);
    }

    __half2 q01  = __floats2half2_rn(a1, a2);
    __half2 q23  = __floats2half2_rn(a3, a4);
    __half2 q01b = __floats2half2_rn(a6, a7);
    __half2 q23b = __floats2half2_rn(a8, a9);
    float4 t0, t1;
    t0.x = a0;
    t0.y = __uint_as_float(*reinterpret_cast<unsigned*>(&q01));
    t0.z = __uint_as_float(*reinterpret_cast<unsigned*>(&q23));
    t0.w = 0.f;
    t1.x = a5;
    t1.y = __uint_as_float(*reinterpret_cast<unsigned*>(&q01b));
    t1.z = __uint_as_float(*reinterpret_cast<unsigned*>(&q23b));
    t1.w = 0.f;
    g_T0[node] = t0;
    g_T1[node] = t1;
}

// ---------------------------------------------------------------------------
// Kernel 2: per-edge, TWO edges per thread with all loads front-batched to
// raise per-thread MLP (3 -> 6-7 outstanding loads) and fill L1tex idle gaps.
// Block of 256 threads covers 512 edges: [blk*512 + tid, blk*512 + 256 + tid].
//   s = p0[row] + p1[col] + sf . (q0[row] + q1[col])
// edge_index is int32 (JAX x64 disabled). Streaming hints protect the L2-
// resident node tables from eviction by the 90MB of streamed data.
// ---------------------------------------------------------------------------
__global__ void edge_kernel(const int* __restrict__ edge_index,
                            const float* __restrict__ sf,
                            const float* __restrict__ gamma_h,
                            const int*   __restrict__ li_ptr,
                            float* __restrict__ out,
                            int n_edges)
{
    __shared__ float s_g[H];
    const int li = li_ptr[0];
    if (threadIdx.x < H) s_g[threadIdx.x] = gamma_h[li * H + threadIdx.x];
    __syncthreads();

    const int tid = threadIdx.x;
    const int e0 = blockIdx.x * 512 + tid;
    const int e1 = e0 + 256;

    const bool v0 = (e0 < n_edges);
    const bool v1 = (e1 < n_edges);

    // ---- front-batched loads (maximize outstanding memory ops) ----
    int row0 = 0, col0 = 0, row1 = 0, col1 = 0;
    if (v0) { row0 = __ldcs(&edge_index[e0]); col0 = __ldcs(&edge_index[n_edges + e0]); }
    if (v1) { row1 = __ldcs(&edge_index[e1]); col1 = __ldcs(&edge_index[n_edges + e1]); }

    float4 f0 = make_float4(0,0,0,0), f1 = make_float4(0,0,0,0);
    if (v0) f0 = __ldcs(reinterpret_cast<const float4*>(sf) + e0);
    if (v1) f1 = __ldcs(reinterpret_cast<const float4*>(sf) + e1);

    float4 R0 = make_float4(0,0,0,0), C0 = make_float4(0,0,0,0);
    float4 R1 = make_float4(0,0,0,0), C1 = make_float4(0,0,0,0);
    if (v0) { R0 = __ldg(&g_T0[row0]); C0 = __ldg(&g_T1[col0]); }
    if (v1) { R1 = __ldg(&g_T0[row1]); C1 = __ldg(&g_T1[col1]); }

    const float g0 = s_g[0], g1 = s_g[1], g2 = s_g[2], g3 = s_g[3];
    const float g4 = s_g[4], g5 = s_g[5], g6 = s_g[6], g7 = s_g[7];

    // ---- edge 0 ----
    if (v0) {
        const __half2 rq01 = *reinterpret_cast<const __half2*>(&R0.y);
        const __half2 rq23 = *reinterpret_cast<const __half2*>(&R0.z);
        const __half2 cq01 = *reinterpret_cast<const __half2*>(&C0.y);
        const __half2 cq23 = *reinterpret_cast<const __half2*>(&C0.z);
        const float2 q01 = __half22float2(__hadd2(rq01, cq01));
        const float2 q23 = __half22float2(__hadd2(rq23, cq23));

        float s = R0.x + C0.x;
        s = fmaf(f0.x, q01.x, s);
        s = fmaf(f0.y, q01.y, s);
        s = fmaf(f0.z, q23.x, s);
        s = fmaf(f0.w, q23.y, s);
        const float base = (s > 0.f) ? s : NEG_SLOPE * s;

        float4* op = reinterpret_cast<float4*>(out + (size_t)e0 * H);
        __stcs(op + 0, make_float4(g0 * base, g1 * base, g2 * base, g3 * base));
        __stcs(op + 1, make_float4(g4 * base, g5 * base, g6 * base, g7 * base));
    }

    // ---- edge 1 ----
    if (v1) {
        const __half2 rq01 = *reinterpret_cast<const __half2*>(&R1.y);
        const __half2 rq23 = *reinterpret_cast<const __half2*>(&R1.z);
        const __half2 cq01 = *reinterpret_cast<const __half2*>(&C1.y);
        const __half2 cq23 = *reinterpret_cast<const __half2*>(&C1.z);
        const float2 q01 = __half22float2(__hadd2(rq01, cq01));
        const float2 q23 = __half22float2(__hadd2(rq23, cq23));

        float s = R1.x + C1.x;
        s = fmaf(f1.x, q01.x, s);
        s = fmaf(f1.y, q01.y, s);
        s = fmaf(f1.z, q23.x, s);
        s = fmaf(f1.w, q23.y, s);
        const float base = (s > 0.f) ? s : NEG_SLOPE * s;

        float4* op = reinterpret_cast<float4*>(out + (size_t)e1 * H);
        __stcs(op + 0, make_float4(g0 * base, g1 * base, g2 * base, g3 * base));
        __stcs(op + 1, make_float4(g4 * base, g5 * base, g6 * base, g7 * base));
    }
}

// ---------------------------------------------------------------------------
// Launch. Input order: x, edge_index, structural_features, layer_idx,
// psi_w, psi_b, delta_w, u, gamma_h.
// ---------------------------------------------------------------------------
extern "C" void kernel_launch(void* const* d_in, const int* in_sizes, int n_in,
                              void* d_out, int out_size)
{
    const float* x    = (const float*)d_in[0];
    const int*   ei   = (const int*)d_in[1];
    const float* sf   = (const float*)d_in[2];
    const int*   li   = (const int*)d_in[3];
    const float* pw   = (const float*)d_in[4];
    const float* pb   = (const float*)d_in[5];
    const float* dw   = (const float*)d_in[6];
    const float* uu   = (const float*)d_in[7];
    const float* gh   = (const float*)d_in[8];
    float*       out  = (float*)d_out;

    const int n_nodes = in_sizes[0] / C;
    const int n_edges = in_sizes[1] / 2;

    // Kernel 1: thread-per-node, 128-node tiles
    {
        const int threads = TILE;
        const int blocks  = (n_nodes + TILE - 1) / TILE;
        node_precompute<<<blocks, threads>>>(x, pw, pb, dw, uu, li, n_nodes);
    }

    // Kernel 2: 2 edges/thread, 512 edges/block
    {
        const int threads = 256;
        const int blocks = (n_edges + 511) / 512;
        edge_kernel<<<blocks, threads>>>(ei, sf, gh, li, out, n_edges);
    }
}